// round 4
// baseline (speedup 1.0000x reference)
#include <cuda_runtime.h>

#define NB   128          // blocks, all co-resident (128 <= 148 SMs)
#define NT   256          // threads per block
#define NCLS 16
#define DIM  128
#define NR   8192
#define RPB  (NR / NB)    // 64 rows per block
#define HP   (RPB / 2)    // 32 feature values held per thread
#define GPITCH 132
#define EPS  1e-6
#define MARGIN 10.0

// ---- persistent scratch (no allocation allowed) ----
__device__ unsigned g_c0, g_c1, g_c2;         // monotone barrier counters (replay-safe)
__device__ float  g_pF[NB][NCLS][DIM];        // per-block class feature sums
__device__ float  g_pS[NB][NCLS];             // per-block class sum-of-squares
__device__ int    g_pC[NB][NCLS];             // per-block class counts
__device__ float  g_Fs[NCLS][DIM];            // reduced class feature sums
__device__ float  g_Sq[NCLS];
__device__ int    g_Ct[NCLS];
__device__ double g_bL[NB], g_bV[NB];         // per-block loss/valid partials

__device__ __forceinline__ void spin_until(volatile unsigned* c, unsigned target) {
    while ((int)(*c - target) < 0) __nanosleep(64);
}

__global__ void __launch_bounds__(NT, 1)
fused_contrastive(const float* __restrict__ f, const int* __restrict__ labw,
                  float* __restrict__ out) {
    __shared__ float s1[2][NCLS][DIM];        // phase1 Fsum partials | phase3: Fs copy (flat)
    __shared__ float s2[2][NCLS][DIM];        // phase1 sq partials
    __shared__ float sG[NCLS][GPITCH];        // phase3 G vectors
    __shared__ int   sLab[RPB];
    __shared__ float sTot[DIM];
    __shared__ float sAl[NCLS], sBe[NCLS], sAv[NCLS], sBv[NCLS], sSq[NCLS];
    __shared__ int   sCt[NCLS];
    __shared__ float sPS[NCLS][8];
    __shared__ int   sPC[NCLS][8];
    __shared__ float sRP[RPB][4], sRQ[RPB][4]; // per-row partial dG / sq (4 dim-warps)
    __shared__ float sWL[2], sWV[2];
    __shared__ float sSqTot;
    __shared__ unsigned sEpoch;
    __shared__ int   sLast;
    __shared__ double rL[NB], rV[NB];

    const int tid  = threadIdx.x;
    const int b    = blockIdx.x;
    const int r0   = b * RPB;
    const int dim  = tid & (DIM - 1);
    const int h    = tid >> 7;                // row-parity handled by this thread
    const int w    = tid >> 5;
    const int lane = tid & 31;

    // ---- issue feature preloads FIRST (DRAM latency covers everything below) --
    float v[HP];
#pragma unroll
    for (int it = 0; it < HP; ++it)
        v[it] = f[(size_t)(r0 + 2 * it + h) * DIM + dim];

    // ---- detect int64 vs int32 labels (256 odd words all-zero => int64) ------
    int acc = labw[2 * tid + 1] | labw[2 * (tid + NT) + 1];
    const int is64 = (__syncthreads_or(acc) == 0);

    // ---- labels for this block; zero partial buffers --------------------------
    if (tid < RPB)
        sLab[tid] = (is64 ? labw[(r0 + tid) << 1] : labw[r0 + tid]) & (NCLS - 1);
    for (int i = tid; i < 2 * NCLS * DIM; i += NT) {
        (&s1[0][0][0])[i] = 0.f;
        (&s2[0][0][0])[i] = 0.f;
    }
    __syncthreads();

    // ---------- Phase 1: per-block class partials ------------------------------
#pragma unroll
    for (int it = 0; it < HP; ++it) {
        const int k = sLab[2 * it + h];
        s1[h][k][dim] += v[it];
        s2[h][k][dim] = fmaf(v[it], v[it], s2[h][k][dim]);
    }
    __syncthreads();

    if (tid < DIM) {
#pragma unroll
        for (int k = 0; k < NCLS; ++k)
            g_pF[b][k][tid] = s1[0][k][tid] + s1[1][k][tid];
    } else {
        const int t = tid - DIM, k = t >> 3, part = t & 7;
        float s = 0.f;
#pragma unroll
        for (int d = 0; d < 16; ++d) {
            const int dd = part * 16 + d;
            s += s2[0][k][dd] + s2[1][k][dd];
        }
        sPS[k][part] = s;
        int c = 0;
#pragma unroll
        for (int r = 0; r < 8; ++r) c += (sLab[part * 8 + r] == k);
        sPC[k][part] = c;
    }
    __syncthreads();
    if (tid < NCLS) {
        float s = 0.f; int c = 0;
#pragma unroll
        for (int p = 0; p < 8; ++p) { s += sPS[tid][p]; c += sPC[tid][p]; }
        g_pS[b][tid] = s;
        g_pC[b][tid] = c;
    }
    __threadfence();
    __syncthreads();
    if (tid == 0) {
        const unsigned tk = atomicAdd(&g_c0, 1u);
        sEpoch = tk / NB;
    }
    __syncthreads();
    const unsigned epoch = sEpoch;
    if (tid == 0) spin_until(&g_c0, (epoch + 1) * NB);
    __syncthreads();
    __threadfence();

    // ---------- Phase 2: ALL 1024 warps reduce 2 (class,dim) entries each ------
    {
        const int wgid = b * 8 + w;           // 0..1023
#pragma unroll
        for (int e = 2 * wgid; e < 2 * wgid + 2; ++e) {
            const int k = e >> 7, d = e & (DIM - 1);
            float s = __ldcg(&g_pF[lane][k][d])
                    + __ldcg(&g_pF[lane + 32][k][d])
                    + __ldcg(&g_pF[lane + 64][k][d])
                    + __ldcg(&g_pF[lane + 96][k][d]);
#pragma unroll
            for (int off = 16; off; off >>= 1)
                s += __shfl_down_sync(0xffffffffu, s, off);
            if (lane == 0) g_Fs[k][d] = s;
        }
        if (b < 2) {                          // Ssq: 16 entries over blocks 0-1
            const int k = b * 8 + w;
            float s = __ldcg(&g_pS[lane][k]) + __ldcg(&g_pS[lane + 32][k])
                    + __ldcg(&g_pS[lane + 64][k]) + __ldcg(&g_pS[lane + 96][k]);
#pragma unroll
            for (int off = 16; off; off >>= 1)
                s += __shfl_down_sync(0xffffffffu, s, off);
            if (lane == 0) g_Sq[k] = s;
        } else if (b < 4) {                   // counts: 16 entries over blocks 2-3
            const int k = (b - 2) * 8 + w;
            int c = __ldcg(&g_pC[lane][k]) + __ldcg(&g_pC[lane + 32][k])
                  + __ldcg(&g_pC[lane + 64][k]) + __ldcg(&g_pC[lane + 96][k]);
#pragma unroll
            for (int off = 16; off; off >>= 1)
                c += __shfl_down_sync(0xffffffffu, c, off);
            if (lane == 0) g_Ct[k] = c;
        }
    }
    __threadfence();
    __syncthreads();
    if (tid == 0) {
        atomicAdd(&g_c1, 1u);
        spin_until(&g_c1, (epoch + 1) * NB);
    }
    __syncthreads();
    __threadfence();

    // ---------- Phase 3 preamble: class constants + G vectors ------------------
    for (int i = tid; i < NCLS * DIM; i += NT)
        (&s1[0][0][0])[i] = __ldcg(&g_Fs[0][0] + i);
    if (tid < NCLS) {
        sCt[tid] = __ldcg(&g_Ct[tid]);
        sSq[tid] = __ldcg(&g_Sq[tid]);
    }
    __syncthreads();
    if (tid < DIM) {
        float t = 0.f;
#pragma unroll
        for (int k = 0; k < NCLS; ++k) t += s1[0][k][tid];
        sTot[tid] = t;
    } else if (tid == NT - 1) {
        double st = 0.0;
#pragma unroll
        for (int k = 0; k < NCLS; ++k) st += (double)sSq[k];
        sSqTot = (float)st;
    }
    __syncthreads();
    if (tid < NCLS) {
        const double cnt = (double)sCt[tid];
        const double c   = cnt - 1.0;
        const double Bv  = 1.0 / ((double)NR - c - 1.0 + EPS);
        const double Av  = 1.0 / (c + EPS) + Bv;
        sAv[tid] = (float)Av;
        sBv[tid] = (float)Bv;
        sAl[tid] = (float)(cnt * Av - (double)NR * Bv);
        sBe[tid] = (float)((double)sSq[tid] * Av - (double)sSqTot * Bv + MARGIN);
    }
    __syncthreads();
    for (int i = tid; i < NCLS * DIM; i += NT) {
        const int k = i >> 7, d = i & (DIM - 1);
        sG[k][d] = sAv[k] * s1[0][k][d] - sBv[k] * sTot[d];
    }
    __syncthreads();

    // ---------- Phase 3: per-row loss using RETAINED registers -----------------
    {
        const int wg = w & 3;                 // which 32-dim group this warp covers
#pragma unroll
        for (int it = 0; it < HP; ++it) {
            const int rloc = 2 * it + h;
            const int k = sLab[rloc];
            float p = v[it] * sG[k][dim];
            float q = v[it] * v[it];
#pragma unroll
            for (int off = 16; off; off >>= 1) {
                p += __shfl_down_sync(0xffffffffu, p, off);
                q += __shfl_down_sync(0xffffffffu, q, off);
            }
            if (lane == 0) { sRP[rloc][wg] = p; sRQ[rloc][wg] = q; }
        }
    }
    __syncthreads();
    {
        float contribL = 0.f, contribV = 0.f;
        if (tid < RPB) {
            const int k = sLab[tid];
            const float dG = (sRP[tid][0] + sRP[tid][1]) + (sRP[tid][2] + sRP[tid][3]);
            const float sq = (sRQ[tid][0] + sRQ[tid][1]) + (sRQ[tid][2] + sRQ[tid][3]);
            const float loss  = fmaf(sAl[k], sq, sBe[k]) - 2.f * dG;
            const float valid = (sCt[k] > 1) ? 1.f : 0.f;
            contribL = fmaxf(loss, 0.f) * valid;
            contribV = valid;
        }
        if (tid < 64) {
#pragma unroll
            for (int off = 16; off; off >>= 1) {
                contribL += __shfl_down_sync(0xffffffffu, contribL, off);
                contribV += __shfl_down_sync(0xffffffffu, contribV, off);
            }
            if (lane == 0) { sWL[w] = contribL; sWV[w] = contribV; }
        }
    }
    __syncthreads();

    // ---------- tail: block partial out; LAST arriving block reduces -----------
    if (tid == 0) {
        g_bL[b] = (double)sWL[0] + (double)sWL[1];
        g_bV[b] = (double)sWV[0] + (double)sWV[1];
        __threadfence();
        const unsigned tk2 = atomicAdd(&g_c2, 1u);
        sLast = (tk2 == (epoch + 1) * NB - 1u);
    }
    __syncthreads();

    if (sLast) {
        __threadfence();
        if (tid < NB) {
            rL[tid] = __ldcg(&g_bL[tid]);
            rV[tid] = __ldcg(&g_bV[tid]);
        }
        __syncthreads();
        for (int off = NB / 2; off; off >>= 1) {
            if (tid < off) { rL[tid] += rL[tid + off]; rV[tid] += rV[tid + off]; }
            __syncthreads();
        }
        if (tid == 0)
            out[0] = (float)(rL[0] / (rV[0] > 1.0 ? rV[0] : 1.0));
    }
}

extern "C" void kernel_launch(void* const* d_in, const int* in_sizes, int n_in,
                              void* d_out, int out_size) {
    const float* f    = (const float*)d_in[0];
    const int*   labw = (const int*)d_in[1];   // int32 or int64 words; detected on-device
    float* out = (float*)d_out;
    fused_contrastive<<<NB, NT>>>(f, labw, out);
}